// round 16
// baseline (speedup 1.0000x reference)
#include <cuda_runtime.h>
#include <cuda_fp16.h>
#include <cstdint>

// ---------------------------------------------------------------------------
// Winograd F(2x2,3x3), FUSED transform+GEMM+output, 2 CTAs/SM.
//   CTA = half a (b,n) row: 32 t x 64 c x 64 k.  Per xy: V tile (32x64,
//   fp16 hi+lo) built in smem (double-buffered), HMMA GEMM vs U_hi
//   (cp.async from L2, double-buffered), A^T M A folded in registers.
//   Channel permutation pi(c) = 8*(c&7) + (c>>3) applied to BOTH V positions
//   and U layout (reduction order irrelevant) -> STS.128 V stores.
//   product = (V_hi + V_lo) * U_hi   (U residual ~2^-11 dropped)
//   Race fix vs R15: cp.async wait_group is executed BEFORE the
//   __syncthreads that precedes the GEMM, so every thread's U(xy) copy is
//   retired before any thread's ldmatrix (canonical wait->barrier->read).
// ---------------------------------------------------------------------------

#define CC 64
#define KK 64

__device__ __half g_Uhi[16 * KK * CC];

// ------------------------------- helpers -----------------------------------
__device__ __forceinline__ uint32_t smem_u32(const void* p) {
    uint32_t a;
    asm("{ .reg .u64 t; cvta.to.shared.u64 t, %1; cvt.u32.u64 %0, t; }"
        : "=r"(a) : "l"(p));
    return a;
}
__device__ __forceinline__ void cpasync16(uint32_t s, const void* g) {
    asm volatile("cp.async.cg.shared.global [%0], [%1], 16;" :: "r"(s), "l"(g));
}
__device__ __forceinline__ void ldm4(uint32_t* r, uint32_t addr) {
    asm volatile("ldmatrix.sync.aligned.m8n8.x4.shared.b16 {%0,%1,%2,%3}, [%4];"
                 : "=r"(r[0]), "=r"(r[1]), "=r"(r[2]), "=r"(r[3]) : "r"(addr));
}
__device__ __forceinline__ void mma16816(float* d, const uint32_t* a,
                                         const uint32_t* b) {
    asm volatile(
        "mma.sync.aligned.m16n8k16.row.col.f32.f16.f16.f32 "
        "{%0,%1,%2,%3}, {%4,%5,%6,%7}, {%8,%9}, {%0,%1,%2,%3};"
        : "+f"(d[0]), "+f"(d[1]), "+f"(d[2]), "+f"(d[3])
        : "r"(a[0]), "r"(a[1]), "r"(a[2]), "r"(a[3]), "r"(b[0]), "r"(b[1]));
}
__device__ __forceinline__ void split2(float a, float b, uint32_t& h, uint32_t& l) {
    __half ha = __float2half(a);
    __half hb = __float2half(b);
    __half la = __float2half(a - __half2float(ha));
    __half lb = __float2half(b - __half2float(hb));
    __half2 hv; hv.x = ha; hv.y = hb;
    __half2 lv; lv.x = la; lv.y = lb;
    h = *(uint32_t*)&hv;
    l = *(uint32_t*)&lv;
}

// ------------------------- kernel 1: weight transform ----------------------
// U stored at permuted position pi(c) = 8*(c&7) + (c>>3).
__global__ void k_weight_transform(const float* __restrict__ w)
{
    int g = blockIdx.x * blockDim.x + threadIdx.x;   // 4096
    if (g >= KK * CC) return;
    int c = g & 63;
    int k = g >> 6;
    int p = ((c & 7) << 3) + (c >> 3);
    const float* wp = w + (k * CC + c) * 9;

    float gm[3][3];
#pragma unroll
    for (int i = 0; i < 3; ++i)
#pragma unroll
        for (int j = 0; j < 3; ++j) gm[i][j] = wp[i * 3 + j];

    float u[4][3];
#pragma unroll
    for (int j = 0; j < 3; ++j) {
        u[0][j] = gm[0][j];
        u[1][j] = 0.5f * (gm[0][j] + gm[1][j] + gm[2][j]);
        u[2][j] = 0.5f * (gm[0][j] - gm[1][j] + gm[2][j]);
        u[3][j] = gm[2][j];
    }
#pragma unroll
    for (int xx = 0; xx < 4; ++xx) {
        float v[4];
        v[0] = u[xx][0];
        v[1] = 0.5f * (u[xx][0] + u[xx][1] + u[xx][2]);
        v[2] = 0.5f * (u[xx][0] - u[xx][1] + u[xx][2]);
        v[3] = u[xx][2];
#pragma unroll
        for (int y = 0; y < 4; ++y)
            g_Uhi[(((xx * 4 + y) * KK + k) << 6) + p] = __float2half(v[y]);
    }
}

// --------------------------- kernel 2: fused -------------------------------
// smem: xs fp32 (64c x [4 rows x 68 + pad] = 274 words/c = 70144 B)
//       V bufs 2 x 9216 (hi 32x144 + lo 32x144) | U bufs 2 x 9216
#define RSTRW  68
#define CSTRW  274
#define XS_BYTES (64 * CSTRW * 4)           // 70144
#define SROW   144
#define VB_OFF  XS_BYTES
#define VHALF   4608                        // 32*144
#define VBUF_SZ 9216
#define UB_OFF  (VB_OFF + 2 * VBUF_SZ)      // 88576
#define UBUF_SZ 9216
#define SMEMSZ  (UB_OFF + 2 * UBUF_SZ)      // 107008

__global__ __launch_bounds__(256, 2) void k_fused(const float* __restrict__ x,
                                                  const float* __restrict__ bias,
                                                  float* __restrict__ out)
{
    extern __shared__ char smraw[];
    const uint32_t sbase = smem_u32(smraw);
    float* xsf = (float*)smraw;

    const int tid  = threadIdx.x;
    const int wid  = tid >> 5;
    const int lane = tid & 31;
    const int bn2  = blockIdx.x;
    const int bn   = bn2 >> 1;
    const int half = bn2 & 1;
    const int b = bn >> 6, n = bn & 63;

    // GEMM geometry (32t x 64k, 8 warps as 2(M) x 4(N), warp 16x16)
    const int m0 = (wid >> 2) << 4;         // 0,16
    const int n0 = (wid & 3) << 4;          // 0,16,32,48
    const int mat = lane >> 3, lrow = lane & 7;
    const int aRow = ((mat & 1) << 3) + lrow;
    const int aCol = (mat >> 1) << 4;
    const int bRow = ((mat >> 1) << 3) + lrow;
    const int bCol = (mat & 1) << 4;

    // transform geometry: thread = (m = tid>>3, tq = tid&7); handles
    // channels c = tq + 8r (r=0..7), stored at V positions 8tq + r.
    const int tm = tid >> 3;
    const int tq = tid & 7;

    // prefetch U(0) while staging x
    {
        const char* gU = (const char*)g_Uhi;
#pragma unroll
        for (int i = 0; i < 2; ++i) {
            int task = tid + i * 256;
            int row = task >> 3, ch = task & 7;
            cpasync16(sbase + UB_OFF + row * SROW + ch * 16, gU + row * 128 + ch * 16);
        }
        asm volatile("cp.async.commit_group;" ::: "memory");
    }

    // stage x slab: 64 c x 4 rows x 66 cols (33 float2 per row)
    for (int i = tid; i < 64 * 132; i += 256) {
        int c = i / 132;
        int rem = i - c * 132;
        int row = rem / 33;
        int j = rem - row * 33;
        float2 v = *(const float2*)(x + ((size_t)(b * 64 + c) * 130 + 2 * n + row) * 130
                                      + 64 * half + 2 * j);
        *(float2*)(xsf + c * CSTRW + row * RSTRW + 2 * j) = v;
    }
    __syncthreads();

    float y00[8], y01[8], y10[8], y11[8];
#pragma unroll
    for (int j = 0; j < 8; ++j) { y00[j] = 0.f; y01[j] = 0.f; y10[j] = 0.f; y11[j] = 0.f; }

    float Z[8][4];   // row-pass values for this thread's 8 channels

#pragma unroll
    for (int xr = 0; xr < 4; ++xr) {
        const int rA = (xr == 0) ? 0 : ((xr == 2) ? 2 : 1);
        const int rB = (xr == 0) ? 2 : ((xr == 1) ? 2 : ((xr == 2) ? 1 : 3));
        const bool addf = (xr == 1);
#pragma unroll
        for (int r = 0; r < 8; ++r) {
            const float* base = xsf + (tq + 8 * r) * CSTRW + 2 * tm;
            float2 a0 = *(const float2*)(base + rA * RSTRW);
            float2 a1 = *(const float2*)(base + rA * RSTRW + 2);
            float2 b0 = *(const float2*)(base + rB * RSTRW);
            float2 b1 = *(const float2*)(base + rB * RSTRW + 2);
            if (addf) {
                Z[r][0] = a0.x + b0.x; Z[r][1] = a0.y + b0.y;
                Z[r][2] = a1.x + b1.x; Z[r][3] = a1.y + b1.y;
            } else {
                Z[r][0] = a0.x - b0.x; Z[r][1] = a0.y - b0.y;
                Z[r][2] = a1.x - b1.x; Z[r][3] = a1.y - b1.y;
            }
        }

#pragma unroll
        for (int yr = 0; yr < 4; ++yr) {
            const int xy = xr * 4 + yr;
            const int p = xy & 1;

            // ---- compute this thread's 8 V values (regs only) ----
            uint32_t h[4], l[4];
#pragma unroll
            for (int rp = 0; rp < 4; ++rp) {
                const int r0 = rp * 2, r1 = rp * 2 + 1;
                float v0 = (yr == 0) ? (Z[r0][0] - Z[r0][2])
                         : (yr == 1) ? (Z[r0][1] + Z[r0][2])
                         : (yr == 2) ? (Z[r0][2] - Z[r0][1])
                         :             (Z[r0][1] - Z[r0][3]);
                float v1 = (yr == 0) ? (Z[r1][0] - Z[r1][2])
                         : (yr == 1) ? (Z[r1][1] + Z[r1][2])
                         : (yr == 2) ? (Z[r1][2] - Z[r1][1])
                         :             (Z[r1][1] - Z[r1][3]);
                split2(v0, v1, h[rp], l[rp]);
            }

            // ---- issue U(xy+1) prefetch, then retire U(xy) locally ----
            if (xy + 1 < 16) {
                const char* gU = (const char*)g_Uhi + ((size_t)(xy + 1) << 13);
                const uint32_t ub = sbase + UB_OFF + ((xy + 1) & 1) * UBUF_SZ;
#pragma unroll
                for (int i = 0; i < 2; ++i) {
                    int task = tid + i * 256;
                    int row = task >> 3, ch = task & 7;
                    cpasync16(ub + row * SROW + ch * 16, gU + row * 128 + ch * 16);
                }
                asm volatile("cp.async.commit_group;" ::: "memory");
                asm volatile("cp.async.wait_group 1;" ::: "memory");   // U(xy) done
            } else {
                asm volatile("cp.async.wait_group 0;" ::: "memory");
            }

            // ---- store V tile (hi/lo) into buffer p ----
            {
                const int off = tm * SROW + tq * 16;
                *(uint4*)(smraw + VB_OFF + p * VBUF_SZ + off) =
                    make_uint4(h[0], h[1], h[2], h[3]);
                *(uint4*)(smraw + VB_OFF + p * VBUF_SZ + VHALF + off) =
                    make_uint4(l[0], l[1], l[2], l[3]);
            }
            // Barrier orders BOTH producers before any consumer:
            // every thread's V stores AND its cp.async wait for U(xy).
            __syncthreads();

            // ---- GEMM this xy (16t x 16k per warp) ----
            const uint32_t vb = sbase + VB_OFF + p * VBUF_SZ;
            const uint32_t ub = sbase + UB_OFF + (xy & 1) * UBUF_SZ;
            float macc[2][4];
#pragma unroll
            for (int bq = 0; bq < 2; ++bq)
#pragma unroll
                for (int cq = 0; cq < 4; ++cq) macc[bq][cq] = 0.f;

#pragma unroll
            for (int kk = 0; kk < 4; ++kk) {
                uint32_t ah[4], al[4], bh[4];
                const uint32_t ra = (m0 + aRow) * SROW + (kk << 5) + aCol;
                ldm4(ah, vb + ra);
                ldm4(al, vb + VHALF + ra);
                const uint32_t rb = (n0 + bRow) * SROW + (kk << 5) + bCol;
                ldm4(bh, ub + rb);
                mma16816(macc[0], ah, &bh[0]);
                mma16816(macc[1], ah, &bh[2]);
                mma16816(macc[0], al, &bh[0]);
                mma16816(macc[1], al, &bh[2]);
            }

            // ---- fold output transform (compile-time coeffs) ----
            const float a0x = (xr == 3) ? 0.f : 1.f;
            const float a1x = (xr == 0) ? 0.f : ((xr == 1) ? 1.f : -1.f);
            const float a0y = (yr == 3) ? 0.f : 1.f;
            const float a1y = (yr == 0) ? 0.f : ((yr == 1) ? 1.f : -1.f);
            const float c00 = a0x * a0y, c01 = a0x * a1y;
            const float c10 = a1x * a0y, c11 = a1x * a1y;
#pragma unroll
            for (int nt = 0; nt < 2; ++nt)
#pragma unroll
                for (int r = 0; r < 4; ++r) {
                    const int e = (nt << 2) + r;
                    const float v = macc[nt][r];
                    if (c00 != 0.f) y00[e] += c00 * v;
                    if (c01 != 0.f) y01[e] += c01 * v;
                    if (c10 != 0.f) y10[e] += c10 * v;
                    if (c11 != 0.f) y11[e] += c11 * v;
                }

            // All warps done reading V(p)/U(xy&1) before xy+1 overwrites:
            // next iteration's prefetch targets U parity (xy)&1 and next V
            // store targets buffer (xy+1)&1 (read at xy-1).
            if (xy < 15) __syncthreads();
        }
    }

    // ---- epilogue: each y element is one (t,k) -> 2x2 output pixels ----
    {
        const int t0g = (bn << 6) + (half << 5);
        const int tb = t0g + m0 + (lane >> 2);
#pragma unroll
        for (int nt = 0; nt < 2; ++nt) {
            const int k0 = n0 + (nt << 3) + ((lane & 3) << 1);
            const float bv0 = __ldg(&bias[k0]);
            const float bv1 = __ldg(&bias[k0 + 1]);
#pragma unroll
            for (int rr = 0; rr < 2; ++rr) {
                const int t = tb + (rr << 3);
                const int bb = t >> 12, nn = (t >> 6) & 63, mm = t & 63;
                float* o0 = out + (((size_t)(bb * KK + k0) * 128 + 2 * nn) * 128 + 2 * mm);
                float* o1 = o0 + 128 * 128;
                const int e = (nt << 2) + (rr << 1);
                *(float2*)o0         = make_float2(y00[e] + bv0,     y01[e] + bv0);
                *(float2*)(o0 + 128) = make_float2(y10[e] + bv0,     y11[e] + bv0);
                *(float2*)o1         = make_float2(y00[e + 1] + bv1, y01[e + 1] + bv1);
                *(float2*)(o1 + 128) = make_float2(y10[e + 1] + bv1, y11[e + 1] + bv1);
            }
        }
    }
}

// ---------------------------------------------------------------------------
extern "C" void kernel_launch(void* const* d_in, const int* in_sizes, int n_in,
                              void* d_out, int out_size)
{
    const float* x    = (const float*)d_in[0];
    const float* w    = (const float*)d_in[1];
    const float* bias = (const float*)d_in[2];
    float* out        = (float*)d_out;

    cudaFuncSetAttribute(k_fused,
                         cudaFuncAttributeMaxDynamicSharedMemorySize, SMEMSZ);

    k_weight_transform<<<16, 256>>>(w);
    k_fused<<<1024, 256, SMEMSZ>>>(x, bias, out);
}

// round 17
// speedup vs baseline: 1.2349x; 1.2349x over previous
#include <cuda_runtime.h>
#include <cuda_fp16.h>
#include <cstdint>

// ---------------------------------------------------------------------------
// Winograd F(2x2,3x3), FUSED transform+GEMM+output, single-pass fp16 HMMA.
//   CTA = half a (b,n) row: 32 t x 64 c x 64 k, 2 CTAs/SM.
//   Per xy: V tile (32x64 fp16, double-buffered smem) built from the
//   smem-staged x slab, one HMMA pass vs U_hi (cp.async, TRIPLE-buffered ->
//   only ONE barrier per xy), A^T M A folded in registers.
//   Error: V and U each truncated to fp16 (~2^-11) -> rel_err ~5e-4.
//   Channel permutation pi(c) = 8*(c&7) + (c>>3) on V positions and U layout.
// ---------------------------------------------------------------------------

#define CC 64
#define KK 64

__device__ __half g_Uhi[16 * KK * CC];

// ------------------------------- helpers -----------------------------------
__device__ __forceinline__ uint32_t smem_u32(const void* p) {
    uint32_t a;
    asm("{ .reg .u64 t; cvta.to.shared.u64 t, %1; cvt.u32.u64 %0, t; }"
        : "=r"(a) : "l"(p));
    return a;
}
__device__ __forceinline__ void cpasync16(uint32_t s, const void* g) {
    asm volatile("cp.async.cg.shared.global [%0], [%1], 16;" :: "r"(s), "l"(g));
}
__device__ __forceinline__ void ldm4(uint32_t* r, uint32_t addr) {
    asm volatile("ldmatrix.sync.aligned.m8n8.x4.shared.b16 {%0,%1,%2,%3}, [%4];"
                 : "=r"(r[0]), "=r"(r[1]), "=r"(r[2]), "=r"(r[3]) : "r"(addr));
}
__device__ __forceinline__ void mma16816(float* d, const uint32_t* a,
                                         const uint32_t* b) {
    asm volatile(
        "mma.sync.aligned.m16n8k16.row.col.f32.f16.f16.f32 "
        "{%0,%1,%2,%3}, {%4,%5,%6,%7}, {%8,%9}, {%0,%1,%2,%3};"
        : "+f"(d[0]), "+f"(d[1]), "+f"(d[2]), "+f"(d[3])
        : "r"(a[0]), "r"(a[1]), "r"(a[2]), "r"(a[3]), "r"(b[0]), "r"(b[1]));
}
__device__ __forceinline__ uint32_t pack2(float a, float b) {
    __half2 hv; hv.x = __float2half(a); hv.y = __float2half(b);
    return *(uint32_t*)&hv;
}

// ------------------------- kernel 1: weight transform ----------------------
// U stored at permuted position pi(c) = 8*(c&7) + (c>>3).
__global__ void k_weight_transform(const float* __restrict__ w)
{
    int g = blockIdx.x * blockDim.x + threadIdx.x;   // 4096
    if (g >= KK * CC) return;
    int c = g & 63;
    int k = g >> 6;
    int p = ((c & 7) << 3) + (c >> 3);
    const float* wp = w + (k * CC + c) * 9;

    float gm[3][3];
#pragma unroll
    for (int i = 0; i < 3; ++i)
#pragma unroll
        for (int j = 0; j < 3; ++j) gm[i][j] = wp[i * 3 + j];

    float u[4][3];
#pragma unroll
    for (int j = 0; j < 3; ++j) {
        u[0][j] = gm[0][j];
        u[1][j] = 0.5f * (gm[0][j] + gm[1][j] + gm[2][j]);
        u[2][j] = 0.5f * (gm[0][j] - gm[1][j] + gm[2][j]);
        u[3][j] = gm[2][j];
    }
#pragma unroll
    for (int xx = 0; xx < 4; ++xx) {
        float v[4];
        v[0] = u[xx][0];
        v[1] = 0.5f * (u[xx][0] + u[xx][1] + u[xx][2]);
        v[2] = 0.5f * (u[xx][0] - u[xx][1] + u[xx][2]);
        v[3] = u[xx][2];
#pragma unroll
        for (int y = 0; y < 4; ++y)
            g_Uhi[(((xx * 4 + y) * KK + k) << 6) + p] = __float2half(v[y]);
    }
}

// --------------------------- kernel 2: fused -------------------------------
// smem: xs fp32 (64c x [4 rows x 68 + pad] = 274 words/c = 70144 B)
//       V bufs 2 x 4608 (32x144) | U bufs 3 x 9216
#define RSTRW  68
#define CSTRW  274
#define XS_BYTES (64 * CSTRW * 4)           // 70144
#define SROW   144
#define VB_OFF  XS_BYTES
#define VBUF_SZ 4608                        // 32*144
#define UB_OFF  (VB_OFF + 2 * VBUF_SZ)      // 79360
#define UBUF_SZ 9216
#define SMEMSZ  (UB_OFF + 3 * UBUF_SZ)      // 107008

__global__ __launch_bounds__(256, 2) void k_fused(const float* __restrict__ x,
                                                  const float* __restrict__ bias,
                                                  float* __restrict__ out)
{
    extern __shared__ char smraw[];
    const uint32_t sbase = smem_u32(smraw);
    float* xsf = (float*)smraw;

    const int tid  = threadIdx.x;
    const int wid  = tid >> 5;
    const int lane = tid & 31;
    const int bn2  = blockIdx.x;
    const int bn   = bn2 >> 1;
    const int half = bn2 & 1;
    const int b = bn >> 6, n = bn & 63;

    // GEMM geometry (32t x 64k, 8 warps as 2(M) x 4(N), warp 16x16)
    const int m0 = (wid >> 2) << 4;         // 0,16
    const int n0 = (wid & 3) << 4;          // 0,16,32,48
    const int mat = lane >> 3, lrow = lane & 7;
    const int aRow = ((mat & 1) << 3) + lrow;
    const int aCol = (mat >> 1) << 4;
    const int bRow = ((mat >> 1) << 3) + lrow;
    const int bCol = (mat & 1) << 4;

    // transform geometry: thread = (m = tid>>3, tq = tid&7); handles
    // channels c = tq + 8r (r=0..7), stored at V positions 8tq + r.
    const int tm = tid >> 3;
    const int tq = tid & 7;

    // prefetch U(0) into buf 0 while staging x
    {
        const char* gU = (const char*)g_Uhi;
#pragma unroll
        for (int i = 0; i < 2; ++i) {
            int task = tid + i * 256;
            int row = task >> 3, ch = task & 7;
            cpasync16(sbase + UB_OFF + row * SROW + ch * 16, gU + row * 128 + ch * 16);
        }
        asm volatile("cp.async.commit_group;" ::: "memory");
    }

    // stage x slab: 64 c x 4 rows x 66 cols (33 float2 per row)
    for (int i = tid; i < 64 * 132; i += 256) {
        int c = i / 132;
        int rem = i - c * 132;
        int row = rem / 33;
        int j = rem - row * 33;
        float2 v = *(const float2*)(x + ((size_t)(b * 64 + c) * 130 + 2 * n + row) * 130
                                      + 64 * half + 2 * j);
        *(float2*)(xsf + c * CSTRW + row * RSTRW + 2 * j) = v;
    }
    __syncthreads();

    float y00[8], y01[8], y10[8], y11[8];
#pragma unroll
    for (int j = 0; j < 8; ++j) { y00[j] = 0.f; y01[j] = 0.f; y10[j] = 0.f; y11[j] = 0.f; }

    float Z[8][4];   // row-pass values for this thread's 8 channels

#pragma unroll
    for (int xr = 0; xr < 4; ++xr) {
        const int rA = (xr == 0) ? 0 : ((xr == 2) ? 2 : 1);
        const int rB = (xr == 0) ? 2 : ((xr == 1) ? 2 : ((xr == 2) ? 1 : 3));
        const bool addf = (xr == 1);
#pragma unroll
        for (int r = 0; r < 8; ++r) {
            const float* base = xsf + (tq + 8 * r) * CSTRW + 2 * tm;
            float2 a0 = *(const float2*)(base + rA * RSTRW);
            float2 a1 = *(const float2*)(base + rA * RSTRW + 2);
            float2 b0 = *(const float2*)(base + rB * RSTRW);
            float2 b1 = *(const float2*)(base + rB * RSTRW + 2);
            if (addf) {
                Z[r][0] = a0.x + b0.x; Z[r][1] = a0.y + b0.y;
                Z[r][2] = a1.x + b1.x; Z[r][3] = a1.y + b1.y;
            } else {
                Z[r][0] = a0.x - b0.x; Z[r][1] = a0.y - b0.y;
                Z[r][2] = a1.x - b1.x; Z[r][3] = a1.y - b1.y;
            }
        }

#pragma unroll
        for (int yr = 0; yr < 4; ++yr) {
            const int xy = xr * 4 + yr;
            const int p = xy & 1;

            // ---- compute this thread's 8 V values, pack to fp16 ----
            uint32_t h[4];
#pragma unroll
            for (int rp = 0; rp < 4; ++rp) {
                const int r0 = rp * 2, r1 = rp * 2 + 1;
                float v0 = (yr == 0) ? (Z[r0][0] - Z[r0][2])
                         : (yr == 1) ? (Z[r0][1] + Z[r0][2])
                         : (yr == 2) ? (Z[r0][2] - Z[r0][1])
                         :             (Z[r0][1] - Z[r0][3]);
                float v1 = (yr == 0) ? (Z[r1][0] - Z[r1][2])
                         : (yr == 1) ? (Z[r1][1] + Z[r1][2])
                         : (yr == 2) ? (Z[r1][2] - Z[r1][1])
                         :             (Z[r1][1] - Z[r1][3]);
                h[rp] = pack2(v0, v1);
            }

            // ---- issue U(xy+1) prefetch (buf (xy+1)%3), retire U(xy) ----
            if (xy + 1 < 16) {
                const char* gU = (const char*)g_Uhi + ((size_t)(xy + 1) << 13);
                const uint32_t ub = sbase + UB_OFF + ((xy + 1) % 3) * UBUF_SZ;
#pragma unroll
                for (int i = 0; i < 2; ++i) {
                    int task = tid + i * 256;
                    int row = task >> 3, ch = task & 7;
                    cpasync16(ub + row * SROW + ch * 16, gU + row * 128 + ch * 16);
                }
                asm volatile("cp.async.commit_group;" ::: "memory");
                asm volatile("cp.async.wait_group 1;" ::: "memory");   // U(xy) done
            } else {
                asm volatile("cp.async.wait_group 0;" ::: "memory");
            }

            // ---- store V tile into buffer p (one STS.128/thread) ----
            *(uint4*)(smraw + VB_OFF + p * VBUF_SZ + tm * SROW + tq * 16) =
                make_uint4(h[0], h[1], h[2], h[3]);

            // Single barrier per xy: orders all V stores and every thread's
            // cp.async wait for U(xy) before any consumer read. Buffer reuse
            // at xy+1 is safe because its prior readers (GEMM xy-1) precede
            // each thread's arrival at THIS barrier.
            __syncthreads();

            // ---- GEMM this xy (16t x 16k per warp, single fp16 pass) ----
            const uint32_t vb = sbase + VB_OFF + p * VBUF_SZ;
            const uint32_t ub = sbase + UB_OFF + (xy % 3) * UBUF_SZ;
            float macc[2][4];
#pragma unroll
            for (int bq = 0; bq < 2; ++bq)
#pragma unroll
                for (int cq = 0; cq < 4; ++cq) macc[bq][cq] = 0.f;

#pragma unroll
            for (int kk = 0; kk < 4; ++kk) {
                uint32_t ah[4], bh[4];
                ldm4(ah, vb + (m0 + aRow) * SROW + (kk << 5) + aCol);
                ldm4(bh, ub + (n0 + bRow) * SROW + (kk << 5) + bCol);
                mma16816(macc[0], ah, &bh[0]);
                mma16816(macc[1], ah, &bh[2]);
            }

            // ---- fold output transform (compile-time coeffs) ----
            const float a0x = (xr == 3) ? 0.f : 1.f;
            const float a1x = (xr == 0) ? 0.f : ((xr == 1) ? 1.f : -1.f);
            const float a0y = (yr == 3) ? 0.f : 1.f;
            const float a1y = (yr == 0) ? 0.f : ((yr == 1) ? 1.f : -1.f);
            const float c00 = a0x * a0y, c01 = a0x * a1y;
            const float c10 = a1x * a0y, c11 = a1x * a1y;
#pragma unroll
            for (int nt = 0; nt < 2; ++nt)
#pragma unroll
                for (int r = 0; r < 4; ++r) {
                    const int e = (nt << 2) + r;
                    const float v = macc[nt][r];
                    if (c00 != 0.f) y00[e] += c00 * v;
                    if (c01 != 0.f) y01[e] += c01 * v;
                    if (c10 != 0.f) y10[e] += c10 * v;
                    if (c11 != 0.f) y11[e] += c11 * v;
                }
        }
    }

    // ---- epilogue: each y element is one (t,k) -> 2x2 output pixels ----
    {
        const int t0g = (bn << 6) + (half << 5);
        const int tb = t0g + m0 + (lane >> 2);
#pragma unroll
        for (int nt = 0; nt < 2; ++nt) {
            const int k0 = n0 + (nt << 3) + ((lane & 3) << 1);
            const float bv0 = __ldg(&bias[k0]);
            const float bv1 = __ldg(&bias[k0 + 1]);
#pragma unroll
            for (int rr = 0; rr < 2; ++rr) {
                const int t = tb + (rr << 3);
                const int bb = t >> 12, nn = (t >> 6) & 63, mm = t & 63;
                float* o0 = out + (((size_t)(bb * KK + k0) * 128 + 2 * nn) * 128 + 2 * mm);
                float* o1 = o0 + 128 * 128;
                const int e = (nt << 2) + (rr << 1);
                *(float2*)o0         = make_float2(y00[e] + bv0,     y01[e] + bv0);
                *(float2*)(o0 + 128) = make_float2(y10[e] + bv0,     y11[e] + bv0);
                *(float2*)o1         = make_float2(y00[e + 1] + bv1, y01[e + 1] + bv1);
                *(float2*)(o1 + 128) = make_float2(y10[e + 1] + bv1, y11[e + 1] + bv1);
            }
        }
    }
}

// ---------------------------------------------------------------------------
extern "C" void kernel_launch(void* const* d_in, const int* in_sizes, int n_in,
                              void* d_out, int out_size)
{
    const float* x    = (const float*)d_in[0];
    const float* w    = (const float*)d_in[1];
    const float* bias = (const float*)d_in[2];
    float* out        = (float*)d_out;

    cudaFuncSetAttribute(k_fused,
                         cudaFuncAttributeMaxDynamicSharedMemorySize, SMEMSZ);

    k_weight_transform<<<16, 256>>>(w);
    k_fused<<<1024, 256, SMEMSZ>>>(x, bias, out);
}